// round 15
// baseline (speedup 1.0000x reference)
#include <cuda_runtime.h>
#include <cuda_fp16.h>
#include <math.h>
#include <stdint.h>

#define Q_CODES   4096
#define E_DIM     256
#define ROWS_TOT  32768

#define BM        128     // rows per CTA (vq + refine)
#define BN        128     // codes per tile
#define NTILES    (Q_CODES / BN)        // 32

#define M_FLAG    4e-4f   // flag margin  (bound 2*maxerr1 ~ 4e-4)
#define M_COLL    5e-4f   // refine collect margin (bound 2*maxerr1, + safety)

// ---- shared smem layout (vq + refine clone) ----
#define XSH_OFF   0                     // 128 x 528B = 67584
#define BST0_OFF  67584                 // 128 codes x 528B = 67584
#define BST1_OFF  135168
#define W2S_OFF   202752                // 4096 floats = 16384 (vq) / 512 used (refine)
#define SREDB_OFF 219136                // 128 u64 = 1024 (vq)
#define SREDS_OFF 220160                // 128 u32 = 512  (vq)
#define VQ_SMEM   220672

#define RSROW_OFF 219136                // refine: 128 ints
#define RF_SMEM   219648

// device scratch
__device__ __half g_wh[Q_CODES * E_DIM];   // scaled by 1024
__device__ float  g_x2[ROWS_TOT];
__device__ float  g_w2[Q_CODES];
__device__ float  g_bestD[ROWS_TOT];
__device__ int    g_bestI[ROWS_TOT];
__device__ int    g_flag[ROWS_TOT];
__device__ int    g_flagrows[ROWS_TOT];
__device__ int    g_nflag;
__device__ unsigned long long g_red[ROWS_TOT];

// ---------------------------------------------------------------------------
__device__ __forceinline__ uint32_t smem_u32(const void* p) {
    uint32_t a;
    asm("{ .reg .u64 t; cvta.to.shared.u64 t, %1; cvt.u32.u64 %0, t; }" : "=r"(a) : "l"(p));
    return a;
}
#define CP_ASYNC16(dst, src) \
    asm volatile("cp.async.cg.shared.global [%0], [%1], 16;" :: "r"(dst), "l"(src))
#define CP_COMMIT() asm volatile("cp.async.commit_group;" ::: "memory")
#define CP_WAIT0()  asm volatile("cp.async.wait_group 0;" ::: "memory")

#define LDMATRIX_X4(r0, r1, r2, r3, addr) \
    asm volatile("ldmatrix.sync.aligned.m8n8.x4.shared.b16 {%0,%1,%2,%3}, [%4];" \
                 : "=r"(r0), "=r"(r1), "=r"(r2), "=r"(r3) : "r"(addr))

__device__ __forceinline__ void mma16816(float* c, const uint32_t* a, const uint32_t* b) {
    asm volatile(
        "mma.sync.aligned.m16n8k16.row.col.f32.f16.f16.f32 "
        "{%0,%1,%2,%3}, {%4,%5,%6,%7}, {%8,%9}, {%0,%1,%2,%3};"
        : "+f"(c[0]), "+f"(c[1]), "+f"(c[2]), "+f"(c[3])
        : "r"(a[0]), "r"(a[1]), "r"(a[2]), "r"(a[3]), "r"(b[0]), "r"(b[1]));
}

// exact R0-numerics distance + candidate commit (noinline: one SASS copy)
__device__ __noinline__ void exact_eval(const float* __restrict__ x,
                                        const float* __restrict__ w,
                                        int row, int code) {
    const float* xr = x + (size_t)row * E_DIM;
    const float* wr = w + (size_t)code * E_DIM;
    float acc = 0.f;
    #pragma unroll 8
    for (int k = 0; k < E_DIM; ++k) acc = fmaf(__ldg(xr + k), __ldg(wr + k), acc);
    float de = fmaf(-2.0f, acc, g_x2[row]) + g_w2[code];
    unsigned long long pack =
        ((unsigned long long)__float_as_uint(de) << 32) | (unsigned)code;
    atomicMin(&g_red[row], pack);
}

// ---------------------------------------------------------------------------
// fused split(w hi, scale 1024) + w2 : warp per code (w2 numerics == R0)
// ---------------------------------------------------------------------------
__global__ void splitw_w2_kernel(const float* __restrict__ w) {
    int code = (blockIdx.x * blockDim.x + threadIdx.x) >> 5;
    int lane = threadIdx.x & 31;
    if (code >= Q_CODES) return;
    const float* row = w + (size_t)code * E_DIM;
    float v[8];
    float s = 0.f;
    #pragma unroll
    for (int j = 0; j < 8; ++j) {
        v[j] = row[lane + 32 * j];
        s = fmaf(v[j], v[j], s);
    }
    #pragma unroll
    for (int off = 16; off; off >>= 1) s += __shfl_down_sync(0xffffffffu, s, off);
    if (lane == 0) g_w2[code] = s;
    #pragma unroll
    for (int j = 0; j < 8; ++j)
        g_wh[(size_t)code * E_DIM + lane + 32 * j] = __float2half_rn(v[j] * 1024.0f);
}

// ---------------------------------------------------------------------------
// B tile (hi): full 128 codes x 256 k per stage; parity = tile & 1
// ---------------------------------------------------------------------------
__device__ __forceinline__ void issue_tile(uint32_t smem_u, int t, int tid) {
    const uint32_t bst = smem_u + ((t & 1) ? BST1_OFF : BST0_OFF);
    const __half* srcH = g_wh + (size_t)(t * BN) * E_DIM;
    #pragma unroll
    for (int it = 0; it < 16; ++it) {
        int i = tid + it * 256;          // 0..4095
        int row = i >> 5, q = i & 31;
        CP_ASYNC16(bst + (uint32_t)(row * 528 + q * 16),
                   (const void*)(srcH + row * E_DIM + q * 8));
    }
}

// ---------------------------------------------------------------------------
// vq pass (unchanged from R14 passing version)
// ---------------------------------------------------------------------------
__global__ __launch_bounds__(256, 1)
void vq_kernel(const float* __restrict__ x) {
    extern __shared__ __align__(128) char smem[];
    const uint32_t smem_u = smem_u32(smem);
    float* w2s = (float*)(smem + W2S_OFF);
    unsigned long long* sredB = (unsigned long long*)(smem + SREDB_OFF);
    unsigned int*       sredS = (unsigned int*)(smem + SREDS_OFF);

    const int tid  = threadIdx.x;
    const int lane = tid & 31;
    const int wid  = tid >> 5;
    const int wm   = wid >> 2;
    const int wn   = wid & 3;
    const int rowBase = blockIdx.x * BM;

    if (blockIdx.x == 0 && tid == 0) g_nflag = 0;

    issue_tile(smem_u, 0, tid);
    CP_COMMIT();

    {   // resident A: convert fp32 x -> half into smem (row stride 528B)
        const float4* xg = (const float4*)(x + (size_t)rowBase * E_DIM);
        #pragma unroll
        for (int it = 0; it < 32; ++it) {
            int i = tid + it * 256;
            int r = i >> 6, q = i & 63;
            float4 v = xg[r * 64 + q];
            __half2 h01 = __halves2half2(__float2half_rn(v.x), __float2half_rn(v.y));
            __half2 h23 = __halves2half2(__float2half_rn(v.z), __float2half_rn(v.w));
            uint2 pk;
            pk.x = *(uint32_t*)&h01;
            pk.y = *(uint32_t*)&h23;
            *(uint2*)(smem + XSH_OFF + r * 528 + q * 8) = pk;
        }
    }
    #pragma unroll
    for (int it = 0; it < 16; ++it) w2s[tid + it * 256] = g_w2[tid + it * 256];
    if (tid < BM) { sredB[tid] = 0xFFFFFFFFFFFFFFFFull; sredS[tid] = 0xFFFFFFFFu; }

    if (tid < BM) {
        const float4* xr4 = (const float4*)(x + (size_t)(rowBase + tid) * E_DIM);
        float s = 0.f;
        #pragma unroll 8
        for (int q = 0; q < 64; ++q) {
            float4 v = __ldg(xr4 + q);
            s = fmaf(v.x, v.x, s);
            s = fmaf(v.y, v.y, s);
            s = fmaf(v.z, v.z, s);
            s = fmaf(v.w, v.w, s);
        }
        g_x2[rowBase + tid] = s;
    }
    __syncthreads();

    float x2r[8];
    #pragma unroll
    for (int mf = 0; mf < 4; ++mf)
        #pragma unroll
        for (int h = 0; h < 2; ++h)
            x2r[mf * 2 + h] = g_x2[rowBase + wm * 64 + mf * 16 + h * 8 + (lane >> 2)];

    float bestD[8], secD[8];
    int   bestI[8];
    #pragma unroll
    for (int i = 0; i < 8; ++i) { bestD[i] = INFINITY; secD[i] = INFINITY; bestI[i] = 0; }

    float acc[4][4][4];

    for (int t = 0; t < NTILES; ++t) {
        CP_WAIT0();
        __syncthreads();
        if (t + 1 < NTILES) { issue_tile(smem_u, t + 1, tid); CP_COMMIT(); }

        const uint32_t bst = smem_u + ((t & 1) ? BST1_OFF : BST0_OFF);

        #pragma unroll
        for (int mf = 0; mf < 4; ++mf)
            #pragma unroll
            for (int nf = 0; nf < 4; ++nf)
                #pragma unroll
                for (int e = 0; e < 4; ++e) acc[mf][nf][e] = 0.f;

        #pragma unroll 4
        for (int kk = 0; kk < 16; ++kk) {
            const int kg = kk * 16;
            uint32_t Ah[4][4], Bh[4][2];
            #pragma unroll
            for (int mf = 0; mf < 4; ++mf) {
                uint32_t off = (uint32_t)((wm * 64 + mf * 16 + (lane & 15)) * 528
                                          + (kg + ((lane >> 4) << 3)) * 2);
                LDMATRIX_X4(Ah[mf][0], Ah[mf][1], Ah[mf][2], Ah[mf][3], smem_u + XSH_OFF + off);
            }
            #pragma unroll
            for (int p = 0; p < 2; ++p) {
                uint32_t n = (uint32_t)(wn * 32 + p * 16 + (lane & 7) + ((lane >> 4) << 3));
                uint32_t off = n * 528 + (uint32_t)((kg + (((lane >> 3) & 1) << 3)) * 2);
                LDMATRIX_X4(Bh[p*2][0], Bh[p*2][1], Bh[p*2+1][0], Bh[p*2+1][1], bst + off);
            }
            #pragma unroll
            for (int mf = 0; mf < 4; ++mf)
                #pragma unroll
                for (int nf = 0; nf < 4; ++nf) mma16816(acc[mf][nf], Ah[mf], Bh[nf]);
        }

        const int codeBase = t * BN + wn * 32;
        #pragma unroll
        for (int mf = 0; mf < 4; ++mf)
            #pragma unroll
            for (int h = 0; h < 2; ++h) {
                const int slot = mf * 2 + h;
                float x2v = x2r[slot];
                float d0 = bestD[slot], d1 = secD[slot];
                int   i0 = bestI[slot];
                #pragma unroll
                for (int nf = 0; nf < 4; ++nf)
                    #pragma unroll
                    for (int j = 0; j < 2; ++j) {
                        int code  = codeBase + nf * 8 + (lane & 3) * 2 + j;
                        float dot = acc[mf][nf][h * 2 + j] * 0.0009765625f;
                        float dv  = fmaf(-2.0f, dot, x2v) + w2s[code];
                        if (dv < d0)      { d1 = d0; d0 = dv; i0 = code; }
                        else if (dv < d1) { d1 = dv; }
                    }
                bestD[slot] = d0; secD[slot] = d1; bestI[slot] = i0;
            }
    }

    __syncthreads();
    #pragma unroll
    for (int i = 0; i < 8; ++i) {
        int rowLocal = wm * 64 + (i >> 1) * 16 + (i & 1) * 8 + (lane >> 2);
        unsigned long long pack =
            ((unsigned long long)__float_as_uint(bestD[i]) << 32) | (unsigned)bestI[i];
        atomicMin(&sredB[rowLocal], pack);
    }
    __syncthreads();
    #pragma unroll
    for (int i = 0; i < 8; ++i) {
        int rowLocal = wm * 64 + (i >> 1) * 16 + (i & 1) * 8 + (lane >> 2);
        unsigned winIdx = (unsigned)(sredB[rowLocal] & 0xffffffffull);
        float cand = ((unsigned)bestI[i] == winIdx) ? secD[i] : bestD[i];
        atomicMin(&sredS[rowLocal], __float_as_uint(cand));
    }
    __syncthreads();

    if (tid < BM) {
        unsigned long long bp = sredB[tid];
        float bd = __uint_as_float((unsigned)(bp >> 32));
        float sd = __uint_as_float(sredS[tid]);
        int row = rowBase + tid;
        g_bestI[row] = (int)(bp & 0xffffffffull);
        g_bestD[row] = bd;
        g_flag[row]  = (sd - bd <= M_FLAG) ? 1 : 0;
    }
}

// ---------------------------------------------------------------------------
// compact: build flagged-row list + init reduction slots (list only)
// ---------------------------------------------------------------------------
__global__ void compact_kernel() {
    int r = blockIdx.x * blockDim.x + threadIdx.x;
    if (r >= ROWS_TOT) return;
    if (!g_flag[r]) return;
    int p = atomicAdd(&g_nflag, 1);
    g_flagrows[p] = r;
    g_red[r] = 0xFFFFFFFFFFFFFFFFull;
}

// ---------------------------------------------------------------------------
// refine: vq-mainloop clone over compacted flagged rows, 1-pass hi*hi.
// item = (group of 128 flagged rows) x (eighth of codes = 4 tiles).
// Candidates (dv <= bestD+M_COLL) -> exact R0 eval + packed atomicMin.
// ---------------------------------------------------------------------------
__global__ __launch_bounds__(256, 1)
void refine_kernel(const float* __restrict__ x, const float* __restrict__ w) {
    extern __shared__ __align__(128) char smem[];
    const uint32_t smem_u = smem_u32(smem);
    float* w2s  = (float*)(smem + W2S_OFF);       // 512 floats (this eighth)
    int*   srow = (int*)(smem + RSROW_OFF);

    const int tid  = threadIdx.x;
    const int lane = tid & 31;
    const int wid  = tid >> 5;
    const int wm   = wid >> 2;
    const int wn   = wid & 3;

    const int nflag = g_nflag;
    const int grpCount = (nflag + 127) >> 7;
    const int item = blockIdx.x;
    if (item >= grpCount * 8) return;
    const int grp = item >> 3, eighth = item & 7;
    const int tile0 = eighth * 4;                 // 4 tiles = 512 codes

    issue_tile(smem_u, tile0, tid);               // tile0 is even -> stage 0
    CP_COMMIT();

    if (tid < BM) {
        int p = grp * BM + tid;
        if (p >= nflag) p = nflag - 1;            // clamp dup: harmless
        srow[tid] = g_flagrows[p];
    }
    __syncthreads();                              // srow ready for A fill

    {   // A fill: gather flagged fp32 rows, convert to half (row stride 528B)
        #pragma unroll
        for (int it = 0; it < 32; ++it) {
            int i = tid + it * 256;
            int r = i >> 6, q = i & 63;
            const float4 v = __ldg((const float4*)(x + (size_t)srow[r] * E_DIM) + q);
            __half2 h01 = __halves2half2(__float2half_rn(v.x), __float2half_rn(v.y));
            __half2 h23 = __halves2half2(__float2half_rn(v.z), __float2half_rn(v.w));
            uint2 pk;
            pk.x = *(uint32_t*)&h01;
            pk.y = *(uint32_t*)&h23;
            *(uint2*)(smem + XSH_OFF + r * 528 + q * 8) = pk;
        }
    }
    w2s[tid]       = g_w2[eighth * 512 + tid];
    w2s[tid + 256] = g_w2[eighth * 512 + 256 + tid];

    // per-slot row info
    int   rid[8]; float x2r[8], thr[8];
    #pragma unroll
    for (int mf = 0; mf < 4; ++mf)
        #pragma unroll
        for (int h = 0; h < 2; ++h) {
            int slot = mf * 2 + h;
            int rl = wm * 64 + mf * 16 + h * 8 + (lane >> 2);
            rid[slot] = srow[rl];
            x2r[slot] = g_x2[rid[slot]];
            thr[slot] = g_bestD[rid[slot]] + M_COLL;
        }

    float acc[4][4][4];

    for (int tt = 0; tt < 4; ++tt) {
        CP_WAIT0();
        __syncthreads();                          // B landed + A fill done (tt=0)
        if (tt + 1 < 4) { issue_tile(smem_u, tile0 + tt + 1, tid); CP_COMMIT(); }

        const uint32_t bst = smem_u + ((tt & 1) ? BST1_OFF : BST0_OFF);

        #pragma unroll
        for (int mf = 0; mf < 4; ++mf)
            #pragma unroll
            for (int nf = 0; nf < 4; ++nf)
                #pragma unroll
                for (int e = 0; e < 4; ++e) acc[mf][nf][e] = 0.f;

        #pragma unroll 4
        for (int kk = 0; kk < 16; ++kk) {
            const int kg = kk * 16;
            uint32_t Ah[4][4], Bh[4][2];
            #pragma unroll
            for (int mf = 0; mf < 4; ++mf) {
                uint32_t off = (uint32_t)((wm * 64 + mf * 16 + (lane & 15)) * 528
                                          + (kg + ((lane >> 4) << 3)) * 2);
                LDMATRIX_X4(Ah[mf][0], Ah[mf][1], Ah[mf][2], Ah[mf][3], smem_u + XSH_OFF + off);
            }
            #pragma unroll
            for (int p = 0; p < 2; ++p) {
                uint32_t n = (uint32_t)(wn * 32 + p * 16 + (lane & 7) + ((lane >> 4) << 3));
                uint32_t off = n * 528 + (uint32_t)((kg + (((lane >> 3) & 1) << 3)) * 2);
                LDMATRIX_X4(Bh[p*2][0], Bh[p*2][1], Bh[p*2+1][0], Bh[p*2+1][1], bst + off);
            }
            #pragma unroll
            for (int mf = 0; mf < 4; ++mf)
                #pragma unroll
                for (int nf = 0; nf < 4; ++nf) mma16816(acc[mf][nf], Ah[mf], Bh[nf]);
        }

        // epilogue: collect candidates -> exact eval (outer loops kept compact)
        const int codeLoc0 = tt * BN + wn * 32;
        #pragma unroll
        for (int mf = 0; mf < 4; ++mf)
            #pragma unroll
            for (int h = 0; h < 2; ++h) {
                const int slot = mf * 2 + h;
                const float x2v = x2r[slot], th = thr[slot];
                #pragma unroll 1
                for (int nf = 0; nf < 4; ++nf)
                    #pragma unroll
                    for (int j = 0; j < 2; ++j) {
                        int cl = codeLoc0 + nf * 8 + (lane & 3) * 2 + j;
                        float dot = acc[mf][nf][h * 2 + j] * 0.0009765625f;
                        float dv  = fmaf(-2.0f, dot, x2v) + w2s[cl];
                        if (dv <= th)
                            exact_eval(x, w, rid[slot], eighth * 512 + cl);
                    }
            }
    }
}

// ---------------------------------------------------------------------------
// gather: 4 rows per 256-thread block
// ---------------------------------------------------------------------------
__global__ void gather_kernel(const float* __restrict__ w, float* __restrict__ out,
                              float* __restrict__ out_idx_f) {
    const int t   = threadIdx.x;
    const int row = blockIdx.x * 4 + (t >> 6);
    const int q   = t & 63;
    int idx = g_flag[row] ? (int)(g_red[row] & 0xffffffffull) : g_bestI[row];
    ((float4*)(out + (size_t)row * E_DIM))[q] =
        ((const float4*)(w + (size_t)idx * E_DIM))[q];
    if (q == 0) out_idx_f[row] = (float)idx;
}

// ---------------------------------------------------------------------------
extern "C" void kernel_launch(void* const* d_in, const int* in_sizes, int n_in,
                              void* d_out, int out_size) {
    const float* x = (const float*)d_in[0];
    const float* w = (const float*)d_in[1];
    int rows = in_sizes[0] / E_DIM;        // 32768

    float* out     = (float*)d_out;
    float* out_idx = out + (size_t)rows * E_DIM;

    cudaFuncSetAttribute(vq_kernel,
                         cudaFuncAttributeMaxDynamicSharedMemorySize, VQ_SMEM);
    cudaFuncSetAttribute(refine_kernel,
                         cudaFuncAttributeMaxDynamicSharedMemorySize, RF_SMEM);

    splitw_w2_kernel<<<Q_CODES / 8, 256>>>(w);                // 1
    vq_kernel<<<rows / BM, 256, VQ_SMEM>>>(x);                // 2
    compact_kernel<<<(ROWS_TOT + 255) / 256, 256>>>();        // 3
    refine_kernel<<<592, 256, RF_SMEM>>>(x, w);               // 4  <- ncu target
    gather_kernel<<<rows / 4, 256>>>(w, out, out_idx);        // 5
}

// round 17
// speedup vs baseline: 1.1687x; 1.1687x over previous
#include <cuda_runtime.h>
#include <cuda_fp16.h>
#include <math.h>
#include <stdint.h>

#define Q_CODES   4096
#define E_DIM     256
#define ROWS_TOT  32768

#define BM        128     // rows per CTA (vq)
#define BN        128     // codes per tile
#define NTILES    (Q_CODES / BN)        // 32

#define M_FLAG    4e-4f   // flag margin  (bound 2*maxerr1 ~ 4e-4)
#define M_COLL    5e-4f   // refine collect margin (bound 2*maxerr1 + safety)

// ---- vq smem offsets: A + 2 full B-tile stages (528B row stride) ----
#define XSH_OFF   0                     // 128 x 528B = 67584
#define BST0_OFF  67584                 // 128 codes x 528B = 67584
#define BST1_OFF  135168
#define W2S_OFF   202752                // 4096 floats = 16384
#define SREDB_OFF 219136                // 128 u64 = 1024
#define SREDS_OFF 220160                // 128 u32 = 512
#define VQ_SMEM   220672

// ---- refine smem offsets (R16: hi-only, compacted) ----
#define RXH_OFF   0                     // 32 x 528 = 16896
#define RB0_OFF   16896                 // 128 codes x 144B = 18432 (hi only)
#define RB1_OFF   35328
#define RW2_OFF   53760                 // 1024 floats = 4096
#define RROW_OFF  57856                 // 32 ints
#define RF_SMEM   57984

#define BS_ROW_BYTES 144                // refine B row stride

// device scratch
__device__ __half g_wh[Q_CODES * E_DIM];   // scaled by 1024
__device__ __half g_xh2[ROWS_TOT * E_DIM]; // compacted flagged rows (hi)
__device__ float  g_x2[ROWS_TOT];
__device__ float  g_w2[Q_CODES];
__device__ float  g_bestD[ROWS_TOT];
__device__ int    g_bestI[ROWS_TOT];
__device__ int    g_flag[ROWS_TOT];
__device__ int    g_flagrows[ROWS_TOT];
__device__ int    g_nflag;
__device__ unsigned long long g_red[ROWS_TOT];

// ---------------------------------------------------------------------------
__device__ __forceinline__ uint32_t smem_u32(const void* p) {
    uint32_t a;
    asm("{ .reg .u64 t; cvta.to.shared.u64 t, %1; cvt.u32.u64 %0, t; }" : "=r"(a) : "l"(p));
    return a;
}
#define CP_ASYNC16(dst, src) \
    asm volatile("cp.async.cg.shared.global [%0], [%1], 16;" :: "r"(dst), "l"(src))
#define CP_COMMIT() asm volatile("cp.async.commit_group;" ::: "memory")
#define CP_WAIT1()  asm volatile("cp.async.wait_group 1;" ::: "memory")
#define CP_WAIT0()  asm volatile("cp.async.wait_group 0;" ::: "memory")

#define LDMATRIX_X4(r0, r1, r2, r3, addr) \
    asm volatile("ldmatrix.sync.aligned.m8n8.x4.shared.b16 {%0,%1,%2,%3}, [%4];" \
                 : "=r"(r0), "=r"(r1), "=r"(r2), "=r"(r3) : "r"(addr))

__device__ __forceinline__ void mma16816(float* c, const uint32_t* a, const uint32_t* b) {
    asm volatile(
        "mma.sync.aligned.m16n8k16.row.col.f32.f16.f16.f32 "
        "{%0,%1,%2,%3}, {%4,%5,%6,%7}, {%8,%9}, {%0,%1,%2,%3};"
        : "+f"(c[0]), "+f"(c[1]), "+f"(c[2]), "+f"(c[3])
        : "r"(a[0]), "r"(a[1]), "r"(a[2]), "r"(a[3]), "r"(b[0]), "r"(b[1]));
}

// exact R0-numerics distance (ascending-k fp32 FMA chain)
__device__ __forceinline__ float exact_dist(const float* __restrict__ x,
                                            const float* __restrict__ w,
                                            int row, int code) {
    const float* xr = x + (size_t)row * E_DIM;
    const float* wr = w + (size_t)code * E_DIM;
    float acc = 0.f;
    #pragma unroll 8
    for (int k = 0; k < E_DIM; ++k) acc = fmaf(__ldg(xr + k), __ldg(wr + k), acc);
    return fmaf(-2.0f, acc, g_x2[row]) + g_w2[code];
}

// ---------------------------------------------------------------------------
// fused split(w hi, scale 1024) + w2 : warp per code (w2 numerics == R0)
// ---------------------------------------------------------------------------
__global__ void splitw_w2_kernel(const float* __restrict__ w) {
    int code = (blockIdx.x * blockDim.x + threadIdx.x) >> 5;
    int lane = threadIdx.x & 31;
    if (code >= Q_CODES) return;
    const float* row = w + (size_t)code * E_DIM;
    float v[8];
    float s = 0.f;
    #pragma unroll
    for (int j = 0; j < 8; ++j) {
        v[j] = row[lane + 32 * j];
        s = fmaf(v[j], v[j], s);
    }
    #pragma unroll
    for (int off = 16; off; off >>= 1) s += __shfl_down_sync(0xffffffffu, s, off);
    if (lane == 0) g_w2[code] = s;
    #pragma unroll
    for (int j = 0; j < 8; ++j)
        g_wh[(size_t)code * E_DIM + lane + 32 * j] = __float2half_rn(v[j] * 1024.0f);
}

// ---------------------------------------------------------------------------
// vq B tile (hi): full 128 codes x 256 k per stage
// ---------------------------------------------------------------------------
__device__ __forceinline__ void vq_issue_tile(uint32_t smem_u, int t, int tid) {
    const uint32_t bst = smem_u + ((t & 1) ? BST1_OFF : BST0_OFF);
    const __half* srcH = g_wh + (size_t)(t * BN) * E_DIM;
    #pragma unroll
    for (int it = 0; it < 16; ++it) {
        int i = tid + it * 256;          // 0..4095
        int row = i >> 5, q = i & 31;
        CP_ASYNC16(bst + (uint32_t)(row * 528 + q * 16),
                   (const void*)(srcH + row * E_DIM + q * 8));
    }
}

// ---------------------------------------------------------------------------
// vq pass (unchanged from R14 passing version)
// ---------------------------------------------------------------------------
__global__ __launch_bounds__(256, 1)
void vq_kernel(const float* __restrict__ x) {
    extern __shared__ __align__(128) char smem[];
    const uint32_t smem_u = smem_u32(smem);
    float* w2s = (float*)(smem + W2S_OFF);
    unsigned long long* sredB = (unsigned long long*)(smem + SREDB_OFF);
    unsigned int*       sredS = (unsigned int*)(smem + SREDS_OFF);

    const int tid  = threadIdx.x;
    const int lane = tid & 31;
    const int wid  = tid >> 5;
    const int wm   = wid >> 2;
    const int wn   = wid & 3;
    const int rowBase = blockIdx.x * BM;

    if (blockIdx.x == 0 && tid == 0) g_nflag = 0;

    vq_issue_tile(smem_u, 0, tid);
    CP_COMMIT();

    {   // resident A: convert fp32 x -> half into smem (row stride 528B)
        const float4* xg = (const float4*)(x + (size_t)rowBase * E_DIM);
        #pragma unroll
        for (int it = 0; it < 32; ++it) {
            int i = tid + it * 256;
            int r = i >> 6, q = i & 63;
            float4 v = xg[r * 64 + q];
            __half2 h01 = __halves2half2(__float2half_rn(v.x), __float2half_rn(v.y));
            __half2 h23 = __halves2half2(__float2half_rn(v.z), __float2half_rn(v.w));
            uint2 pk;
            pk.x = *(uint32_t*)&h01;
            pk.y = *(uint32_t*)&h23;
            *(uint2*)(smem + XSH_OFF + r * 528 + q * 8) = pk;
        }
    }
    #pragma unroll
    for (int it = 0; it < 16; ++it) w2s[tid + it * 256] = g_w2[tid + it * 256];
    if (tid < BM) { sredB[tid] = 0xFFFFFFFFFFFFFFFFull; sredS[tid] = 0xFFFFFFFFu; }

    if (tid < BM) {
        const float4* xr4 = (const float4*)(x + (size_t)(rowBase + tid) * E_DIM);
        float s = 0.f;
        #pragma unroll 8
        for (int q = 0; q < 64; ++q) {
            float4 v = __ldg(xr4 + q);
            s = fmaf(v.x, v.x, s);
            s = fmaf(v.y, v.y, s);
            s = fmaf(v.z, v.z, s);
            s = fmaf(v.w, v.w, s);
        }
        g_x2[rowBase + tid] = s;
    }
    __syncthreads();

    float x2r[8];
    #pragma unroll
    for (int mf = 0; mf < 4; ++mf)
        #pragma unroll
        for (int h = 0; h < 2; ++h)
            x2r[mf * 2 + h] = g_x2[rowBase + wm * 64 + mf * 16 + h * 8 + (lane >> 2)];

    float bestD[8], secD[8];
    int   bestI[8];
    #pragma unroll
    for (int i = 0; i < 8; ++i) { bestD[i] = INFINITY; secD[i] = INFINITY; bestI[i] = 0; }

    float acc[4][4][4];

    for (int t = 0; t < NTILES; ++t) {
        CP_WAIT0();
        __syncthreads();
        if (t + 1 < NTILES) { vq_issue_tile(smem_u, t + 1, tid); CP_COMMIT(); }

        const uint32_t bst = smem_u + ((t & 1) ? BST1_OFF : BST0_OFF);

        #pragma unroll
        for (int mf = 0; mf < 4; ++mf)
            #pragma unroll
            for (int nf = 0; nf < 4; ++nf)
                #pragma unroll
                for (int e = 0; e < 4; ++e) acc[mf][nf][e] = 0.f;

        #pragma unroll 4
        for (int kk = 0; kk < 16; ++kk) {
            const int kg = kk * 16;
            uint32_t Ah[4][4], Bh[4][2];
            #pragma unroll
            for (int mf = 0; mf < 4; ++mf) {
                uint32_t off = (uint32_t)((wm * 64 + mf * 16 + (lane & 15)) * 528
                                          + (kg + ((lane >> 4) << 3)) * 2);
                LDMATRIX_X4(Ah[mf][0], Ah[mf][1], Ah[mf][2], Ah[mf][3], smem_u + XSH_OFF + off);
            }
            #pragma unroll
            for (int p = 0; p < 2; ++p) {
                uint32_t n = (uint32_t)(wn * 32 + p * 16 + (lane & 7) + ((lane >> 4) << 3));
                uint32_t off = n * 528 + (uint32_t)((kg + (((lane >> 3) & 1) << 3)) * 2);
                LDMATRIX_X4(Bh[p*2][0], Bh[p*2][1], Bh[p*2+1][0], Bh[p*2+1][1], bst + off);
            }
            #pragma unroll
            for (int mf = 0; mf < 4; ++mf)
                #pragma unroll
                for (int nf = 0; nf < 4; ++nf) mma16816(acc[mf][nf], Ah[mf], Bh[nf]);
        }

        const int codeBase = t * BN + wn * 32;
        #pragma unroll
        for (int mf = 0; mf < 4; ++mf)
            #pragma unroll
            for (int h = 0; h < 2; ++h) {
                const int slot = mf * 2 + h;
                float x2v = x2r[slot];
                float d0 = bestD[slot], d1 = secD[slot];
                int   i0 = bestI[slot];
                #pragma unroll
                for (int nf = 0; nf < 4; ++nf)
                    #pragma unroll
                    for (int j = 0; j < 2; ++j) {
                        int code  = codeBase + nf * 8 + (lane & 3) * 2 + j;
                        float dot = acc[mf][nf][h * 2 + j] * 0.0009765625f;
                        float dv  = fmaf(-2.0f, dot, x2v) + w2s[code];
                        if (dv < d0)      { d1 = d0; d0 = dv; i0 = code; }
                        else if (dv < d1) { d1 = dv; }
                    }
                bestD[slot] = d0; secD[slot] = d1; bestI[slot] = i0;
            }
    }

    __syncthreads();
    #pragma unroll
    for (int i = 0; i < 8; ++i) {
        int rowLocal = wm * 64 + (i >> 1) * 16 + (i & 1) * 8 + (lane >> 2);
        unsigned long long pack =
            ((unsigned long long)__float_as_uint(bestD[i]) << 32) | (unsigned)bestI[i];
        atomicMin(&sredB[rowLocal], pack);
    }
    __syncthreads();
    #pragma unroll
    for (int i = 0; i < 8; ++i) {
        int rowLocal = wm * 64 + (i >> 1) * 16 + (i & 1) * 8 + (lane >> 2);
        unsigned winIdx = (unsigned)(sredB[rowLocal] & 0xffffffffull);
        float cand = ((unsigned)bestI[i] == winIdx) ? secD[i] : bestD[i];
        atomicMin(&sredS[rowLocal], __float_as_uint(cand));
    }
    __syncthreads();

    if (tid < BM) {
        unsigned long long bp = sredB[tid];
        float bd = __uint_as_float((unsigned)(bp >> 32));
        float sd = __uint_as_float(sredS[tid]);
        int row = rowBase + tid;
        g_bestI[row] = (int)(bp & 0xffffffffull);
        g_bestD[row] = bd;
        g_flag[row]  = (sd - bd <= M_FLAG) ? 1 : 0;
    }
}

// ---------------------------------------------------------------------------
// fused compact + row copy (hi only): flagging thread claims slot, copies row
// ---------------------------------------------------------------------------
__global__ void compactcopy_kernel(const float* __restrict__ x) {
    int r = blockIdx.x * blockDim.x + threadIdx.x;
    if (r >= ROWS_TOT) return;
    if (!g_flag[r]) return;
    int p = atomicAdd(&g_nflag, 1);
    g_flagrows[p] = r;
    g_red[r] = 0xFFFFFFFFFFFFFFFFull;

    const float4* src = (const float4*)(x + (size_t)r * E_DIM);
    __half2* dh = (__half2*)(g_xh2 + (size_t)p * E_DIM);
    #pragma unroll 4
    for (int q = 0; q < 64; ++q) {
        float4 v4 = __ldg(src + q);
        dh[q * 2]     = __halves2half2(__float2half_rn(v4.x), __float2half_rn(v4.y));
        dh[q * 2 + 1] = __halves2half2(__float2half_rn(v4.z), __float2half_rn(v4.w));
    }
}

// ---------------------------------------------------------------------------
// refine B chunk (hi only): 128 codes x 64 k, row stride 144B
// ---------------------------------------------------------------------------
__device__ __forceinline__ void rf_issue_chunk(uint32_t smem_u, int quarter, int s, int tid) {
    const int t = s >> 2, c = s & 3;
    const int codeBase = quarter * 1024 + t * BN;
    const uint32_t bst = smem_u + ((s & 1) ? RB1_OFF : RB0_OFF);
    const __half* srcH = g_wh + (size_t)codeBase * E_DIM + c * 64;
    #pragma unroll
    for (int it = 0; it < 4; ++it) {
        int i = tid + it * 256;
        int row = i >> 3, q = i & 7;
        CP_ASYNC16(bst + (uint32_t)(row * BS_ROW_BYTES + q * 16),
                   (const void*)(srcH + row * E_DIM + q * 8));
    }
}

// ---------------------------------------------------------------------------
// refine: R14 skeleton, 1-pass hi*hi; candidates (dv <= bestD+M_COLL) -> exact
// item = (group of 32 flagged rows) x (quarter of codes). grid-stride.
// ---------------------------------------------------------------------------
__global__ __launch_bounds__(256, 1)
void refine_kernel(const float* __restrict__ x, const float* __restrict__ w) {
    extern __shared__ __align__(128) char smem[];
    const uint32_t smem_u = smem_u32(smem);
    float* w2q  = (float*)(smem + RW2_OFF);
    int*   srow = (int*)(smem + RROW_OFF);

    const int tid  = threadIdx.x;
    const int lane = tid & 31;
    const int wid  = tid >> 5;
    const int wm   = wid >> 2;          // 0..1 -> 16 rows each
    const int wn   = wid & 3;

    const int nflag  = g_nflag;
    const int nItems = ((nflag + 31) >> 5) * 4;

    for (int item = blockIdx.x; item < nItems; item += gridDim.x) {
        const int grp = item >> 2, quarter = item & 3;
        __syncthreads();                 // smem reuse across items

        rf_issue_chunk(smem_u, quarter, 0, tid);
        CP_COMMIT();

        // compacted A rows (hi), 32 rows x 32 uint4, row stride 528B
        #pragma unroll
        for (int it = 0; it < 4; ++it) {
            int i = tid + it * 256;      // 0..1023
            int r = i >> 5, q = i & 31;
            int p = grp * 32 + r; if (p >= nflag) p = nflag - 1;
            *(uint4*)(smem + RXH_OFF + r * 528 + q * 16) =
                ((const uint4*)(g_xh2 + (size_t)p * E_DIM))[q];
        }
        #pragma unroll
        for (int it = 0; it < 4; ++it)
            w2q[tid + it * 256] = g_w2[quarter * 1024 + tid + it * 256];
        if (tid < 32) {
            int p = grp * 32 + tid; if (p >= nflag) p = nflag - 1;
            srow[tid] = g_flagrows[p];
        }
        __syncthreads();

        int   rid[2]; float x2v[2], thr[2];
        #pragma unroll
        for (int h = 0; h < 2; ++h) {
            int rl = wm * 16 + h * 8 + (lane >> 2);
            rid[h] = srow[rl];
            x2v[h] = g_x2[rid[h]];
            thr[h] = g_bestD[rid[h]] + M_COLL;
        }

        for (int t = 0; t < 8; ++t) {
            float acc[4][4];
            #pragma unroll
            for (int nf = 0; nf < 4; ++nf)
                #pragma unroll
                for (int e = 0; e < 4; ++e) acc[nf][e] = 0.f;

            for (int c = 0; c < 4; ++c) {
                const int s = t * 4 + c;
                if (s + 1 < 32) { rf_issue_chunk(smem_u, quarter, s + 1, tid); CP_COMMIT(); CP_WAIT1(); }
                else            { CP_WAIT0(); }
                __syncthreads();

                const uint32_t bst = smem_u + ((s & 1) ? RB1_OFF : RB0_OFF);

                #pragma unroll
                for (int kk = 0; kk < 4; ++kk) {
                    const int kg = c * 64 + kk * 16;
                    const int kl = kk * 16;
                    uint32_t Ah[4], Bh[4][2];
                    {
                        uint32_t off = (uint32_t)((wm * 16 + (lane & 15)) * 528
                                                  + (kg + ((lane >> 4) << 3)) * 2);
                        LDMATRIX_X4(Ah[0], Ah[1], Ah[2], Ah[3], smem_u + RXH_OFF + off);
                    }
                    #pragma unroll
                    for (int p = 0; p < 2; ++p) {
                        uint32_t n = (uint32_t)(wn * 32 + p * 16 + (lane & 7) + ((lane >> 4) << 3));
                        uint32_t off = n * BS_ROW_BYTES + (uint32_t)((kl + (((lane >> 3) & 1) << 3)) * 2);
                        LDMATRIX_X4(Bh[p*2][0], Bh[p*2][1], Bh[p*2+1][0], Bh[p*2+1][1], bst + off);
                    }
                    #pragma unroll
                    for (int nf = 0; nf < 4; ++nf) mma16816(acc[nf], Ah, Bh[nf]);
                }
                __syncthreads();
            }

            const int codeBase = quarter * 1024 + t * BN + wn * 32;
            #pragma unroll
            for (int h = 0; h < 2; ++h)
                #pragma unroll
                for (int nf = 0; nf < 4; ++nf)
                    #pragma unroll
                    for (int j = 0; j < 2; ++j) {
                        int code  = codeBase + nf * 8 + (lane & 3) * 2 + j;
                        float dot = acc[nf][h * 2 + j] * 0.0009765625f;
                        float dv  = fmaf(-2.0f, dot, x2v[h]) + w2q[t * BN + wn * 32 + nf * 8 + (lane & 3) * 2 + j];
                        if (dv <= thr[h]) {
                            float de = exact_dist(x, w, rid[h], code);
                            unsigned long long pack =
                                ((unsigned long long)__float_as_uint(de) << 32) | (unsigned)code;
                            atomicMin(&g_red[rid[h]], pack);
                        }
                    }
        }
    }
}

// ---------------------------------------------------------------------------
// gather: 4 rows per 256-thread block
// ---------------------------------------------------------------------------
__global__ void gather_kernel(const float* __restrict__ w, float* __restrict__ out,
                              float* __restrict__ out_idx_f) {
    const int t   = threadIdx.x;
    const int row = blockIdx.x * 4 + (t >> 6);
    const int q   = t & 63;
    int idx = g_flag[row] ? (int)(g_red[row] & 0xffffffffull) : g_bestI[row];
    ((float4*)(out + (size_t)row * E_DIM))[q] =
        ((const float4*)(w + (size_t)idx * E_DIM))[q];
    if (q == 0) out_idx_f[row] = (float)idx;
}

// ---------------------------------------------------------------------------
extern "C" void kernel_launch(void* const* d_in, const int* in_sizes, int n_in,
                              void* d_out, int out_size) {
    const float* x = (const float*)d_in[0];
    const float* w = (const float*)d_in[1];
    int rows = in_sizes[0] / E_DIM;        // 32768

    float* out     = (float*)d_out;
    float* out_idx = out + (size_t)rows * E_DIM;

    cudaFuncSetAttribute(vq_kernel,
                         cudaFuncAttributeMaxDynamicSharedMemorySize, VQ_SMEM);
    cudaFuncSetAttribute(refine_kernel,
                         cudaFuncAttributeMaxDynamicSharedMemorySize, RF_SMEM);

    splitw_w2_kernel<<<Q_CODES / 8, 256>>>(w);                // 1
    vq_kernel<<<rows / BM, 256, VQ_SMEM>>>(x);                // 2
    compactcopy_kernel<<<(ROWS_TOT + 255) / 256, 256>>>(x);   // 3
    refine_kernel<<<592, 256, RF_SMEM>>>(x, w);               // 4  <- ncu target
    gather_kernel<<<rows / 4, 256>>>(w, out, out_idx);        // 5
}